// round 2
// baseline (speedup 1.0000x reference)
#include <cuda_runtime.h>
#include <math.h>

#define BB 32
#define TT 1024
#define DD 512
#define KK 64
#define OO 1024
#define F_EPS 1e-12f

// Scratch (device globals — no allocation allowed)
__device__ float g_a[BB * TT * KK];      // soft-assign [B,T,K]  (8 MB)
__device__ float g_agg[BB * KK * DD];    // x_agg [B,K,D] (4 MB)
__device__ float g_vt[KK * DD * BB];     // normalized v, TRANSPOSED [kd][b] (4 MB)
__device__ float g_sumw[BB * KK];        // per-(b,k) soft weight sums
__device__ float g_norm2[BB];            // per-b squared norm after intra-norm

// ---------------------------------------------------------------------------
// K1: logits = x @ W + bias, softmax over K, write a, accumulate sum_w.
// Block: 128 rows x 64 centers, 256 threads, thread tile 4 rows x 8 k.
// ---------------------------------------------------------------------------
__global__ __launch_bounds__(256) void k_assign(const float* __restrict__ x,
                                                const float* __restrict__ w,
                                                const float* __restrict__ bias) {
    __shared__ float xs[128 * 33];
    __shared__ __align__(16) float ws[32 * 64];
    __shared__ float bias_s[64];
    __shared__ float ssum[64];

    const int tid = threadIdx.x;
    const int r0 = blockIdx.x * 128;          // global row base (b*T + t)
    const int kg = tid & 7;                   // k-group (8 groups of 8 k)
    const int rg = tid >> 3;                  // row-group (32 groups of 4 rows)
    const int k8 = kg * 8;
    const int r4 = rg * 4;

    if (tid < 64) { ssum[tid] = 0.0f; bias_s[tid] = bias[tid]; }

    float acc[4][8];
#pragma unroll
    for (int i = 0; i < 4; i++)
#pragma unroll
        for (int j = 0; j < 8; j++) acc[i][j] = 0.0f;

    for (int d0 = 0; d0 < DD; d0 += 32) {
        // x tile [128 rows x 32 d] (padded stride 33)
#pragma unroll
        for (int i = 0; i < 4; i++) {
            int idx = tid + i * 256;          // float4 index 0..1023
            int row = idx >> 3;
            int dc  = (idx & 7) * 4;
            float4 v = *(const float4*)&x[(size_t)(r0 + row) * DD + d0 + dc];
            xs[row * 33 + dc + 0] = v.x;
            xs[row * 33 + dc + 1] = v.y;
            xs[row * 33 + dc + 2] = v.z;
            xs[row * 33 + dc + 3] = v.w;
        }
        // W tile: 2048 contiguous floats at w + d0*64
#pragma unroll
        for (int i = 0; i < 2; i++) {
            int idx = tid + i * 256;
            *(float4*)&ws[idx * 4] = *(const float4*)&w[(size_t)d0 * KK + idx * 4];
        }
        __syncthreads();

#pragma unroll 4
        for (int d = 0; d < 32; d++) {
            float4 w0 = *(float4*)&ws[d * 64 + k8];
            float4 w1 = *(float4*)&ws[d * 64 + k8 + 4];
            float xv[4];
#pragma unroll
            for (int i = 0; i < 4; i++) xv[i] = xs[(r4 + i) * 33 + d];
#pragma unroll
            for (int i = 0; i < 4; i++) {
                acc[i][0] = fmaf(xv[i], w0.x, acc[i][0]);
                acc[i][1] = fmaf(xv[i], w0.y, acc[i][1]);
                acc[i][2] = fmaf(xv[i], w0.z, acc[i][2]);
                acc[i][3] = fmaf(xv[i], w0.w, acc[i][3]);
                acc[i][4] = fmaf(xv[i], w1.x, acc[i][4]);
                acc[i][5] = fmaf(xv[i], w1.y, acc[i][5]);
                acc[i][6] = fmaf(xv[i], w1.z, acc[i][6]);
                acc[i][7] = fmaf(xv[i], w1.w, acc[i][7]);
            }
        }
        __syncthreads();
    }

    // softmax per row: 64 logits spread over 8 lanes (kg) x 8 regs
    float colsum[8];
#pragma unroll
    for (int j = 0; j < 8; j++) colsum[j] = 0.0f;
#pragma unroll
    for (int i = 0; i < 4; i++) {
        float v[8];
        float m = -1e30f;
#pragma unroll
        for (int j = 0; j < 8; j++) {
            v[j] = acc[i][j] + bias_s[k8 + j];
            m = fmaxf(m, v[j]);
        }
#pragma unroll
        for (int off = 4; off > 0; off >>= 1)
            m = fmaxf(m, __shfl_xor_sync(0xffffffffu, m, off));
        float s = 0.0f;
#pragma unroll
        for (int j = 0; j < 8; j++) { v[j] = __expf(v[j] - m); s += v[j]; }
#pragma unroll
        for (int off = 4; off > 0; off >>= 1)
            s += __shfl_xor_sync(0xffffffffu, s, off);
        float inv = 1.0f / s;
        float4 a0, a1;
        a0.x = v[0] * inv; a0.y = v[1] * inv; a0.z = v[2] * inv; a0.w = v[3] * inv;
        a1.x = v[4] * inv; a1.y = v[5] * inv; a1.z = v[6] * inv; a1.w = v[7] * inv;
        colsum[0] += a0.x; colsum[1] += a0.y; colsum[2] += a0.z; colsum[3] += a0.w;
        colsum[4] += a1.x; colsum[5] += a1.y; colsum[6] += a1.z; colsum[7] += a1.w;
        *(float4*)&g_a[(size_t)(r0 + r4 + i) * KK + k8] = a0;
        *(float4*)&g_a[(size_t)(r0 + r4 + i) * KK + k8 + 4] = a1;
    }

    // reduce colsum over the 4 rg-groups in this warp, then smem atomics
#pragma unroll
    for (int j = 0; j < 8; j++) {
        colsum[j] += __shfl_xor_sync(0xffffffffu, colsum[j], 8);
        colsum[j] += __shfl_xor_sync(0xffffffffu, colsum[j], 16);
    }
    if ((tid & 31) < 8) {
#pragma unroll
        for (int j = 0; j < 8; j++) atomicAdd(&ssum[k8 + j], colsum[j]);
    }
    __syncthreads();
    if (tid < 64) atomicAdd(&g_sumw[(r0 >> 10) * KK + tid], ssum[tid]);
}

// ---------------------------------------------------------------------------
// K2: x_agg[b,k,d] = sum_t a[b,t,k] * x[b,t,d]
// grid: b(32) x dtile(4 of 128) x tseg(4 of 256) = 512 blocks, 128 threads.
// ---------------------------------------------------------------------------
__global__ __launch_bounds__(128) void k_agg(const float* __restrict__ x) {
    __shared__ __align__(16) float as[16 * 64];
    const int tid = threadIdx.x;
    const int bx = blockIdx.x;
    const int b   = bx >> 4;
    const int dt  = (bx >> 2) & 3;
    const int seg = bx & 3;
    const int d   = dt * 128 + tid;
    const int t0  = seg * 256;

    float acc[64];
#pragma unroll
    for (int k = 0; k < 64; k++) acc[k] = 0.0f;

    for (int tt0 = 0; tt0 < 256; tt0 += 16) {
#pragma unroll
        for (int i = 0; i < 2; i++) {
            int idx = tid + i * 128;
            *(float4*)&as[idx * 4] =
                *(const float4*)&g_a[(size_t)(b * TT + t0 + tt0) * KK + idx * 4];
        }
        __syncthreads();
#pragma unroll 2
        for (int tt = 0; tt < 16; tt++) {
            float xv = x[(size_t)(b * TT + t0 + tt0 + tt) * DD + d];
#pragma unroll
            for (int kk = 0; kk < 16; kk++) {
                float4 av = *(float4*)&as[tt * 64 + kk * 4];
                acc[kk * 4 + 0] = fmaf(av.x, xv, acc[kk * 4 + 0]);
                acc[kk * 4 + 1] = fmaf(av.y, xv, acc[kk * 4 + 1]);
                acc[kk * 4 + 2] = fmaf(av.z, xv, acc[kk * 4 + 2]);
                acc[kk * 4 + 3] = fmaf(av.w, xv, acc[kk * 4 + 3]);
            }
        }
        __syncthreads();
    }
#pragma unroll
    for (int k = 0; k < 64; k++)
        atomicAdd(&g_agg[((size_t)b * KK + k) * DD + d], acc[k]);
}

// ---------------------------------------------------------------------------
// K3: residual + intra L2-normalize per (b,k); write v TRANSPOSED to g_vt[kd][b]
// ---------------------------------------------------------------------------
__global__ __launch_bounds__(128) void k_norm(const float* __restrict__ centers) {
    const int bx = blockIdx.x;                // 2048 = B*K
    const int b = bx >> 6;
    const int k = bx & 63;
    const int tid = threadIdx.x;

    const float sw = g_sumw[b * KK + k];
    const size_t base = ((size_t)b * KK + k) * DD;

    float4 xa = *(float4*)&g_agg[base + tid * 4];
    float4 c  = *(const float4*)&centers[(size_t)k * DD + tid * 4];
    float4 f;
    f.x = xa.x - sw * c.x;
    f.y = xa.y - sw * c.y;
    f.z = xa.z - sw * c.z;
    f.w = xa.w - sw * c.w;
    float ss = f.x * f.x + f.y * f.y + f.z * f.z + f.w * f.w;

#pragma unroll
    for (int off = 16; off > 0; off >>= 1)
        ss += __shfl_xor_sync(0xffffffffu, ss, off);

    __shared__ float wsum[4];
    __shared__ float scale_s;
    if ((tid & 31) == 0) wsum[tid >> 5] = ss;
    __syncthreads();
    if (tid == 0) {
        float tot = wsum[0] + wsum[1] + wsum[2] + wsum[3];
        float sc = rsqrtf(fmaxf(tot, F_EPS));
        scale_s = sc;
        atomicAdd(&g_norm2[b], tot * sc * sc);
    }
    __syncthreads();
    float sc = scale_s;
    const int d = tid * 4;
    const size_t vbase = ((size_t)k * DD + d) * BB + b;
    g_vt[vbase + 0 * BB] = f.x * sc;
    g_vt[vbase + 1 * BB] = f.y * sc;
    g_vt[vbase + 2 * BB] = f.z * sc;
    g_vt[vbase + 3 * BB] = f.w * sc;
}

// ---------------------------------------------------------------------------
// K4: out[b,o] += sum_kd v[b,kd] * R[kd,o]
// grid: 8 o-tiles(128) x 32 kd-chunks(1024) = 256 blocks, 128 threads.
// Thread tile: 4 b x 8 o. Double-buffered smem, one sync per 32-kd chunk.
// ---------------------------------------------------------------------------
__global__ __launch_bounds__(128) void k_out(const float* __restrict__ R,
                                             float* __restrict__ out) {
    __shared__ __align__(16) float vs[2][32 * 36];   // [kd][b]
    __shared__ __align__(16) float rs[2][32 * 132];  // [kd][o]

    const int tid = threadIdx.x;
    const int bx = blockIdx.x;
    const int o0  = (bx & 7) * 128;
    const int kd0 = (bx >> 3) * 1024;
    const int bq = tid & 7;        // b = bq*4 + i
    const int oq = tid >> 3;       // o = o0 + oq*8 + j

    float acc[4][8];
#pragma unroll
    for (int i = 0; i < 4; i++)
#pragma unroll
        for (int j = 0; j < 8; j++) acc[i][j] = 0.0f;

#define LOAD_CHUNK(c, p)                                                         \
    do {                                                                         \
        const float4* vsrc = (const float4*)&g_vt[(size_t)(kd0 + (c) * 32) * BB];\
        _Pragma("unroll")                                                        \
        for (int i_ = 0; i_ < 2; i_++) {                                         \
            int idx = tid + i_ * 128;                                            \
            int kd = idx >> 3; int bc = (idx & 7) * 4;                           \
            *(float4*)&vs[p][kd * 36 + bc] = vsrc[idx];                          \
        }                                                                        \
        _Pragma("unroll")                                                        \
        for (int i_ = 0; i_ < 8; i_++) {                                         \
            int idx = tid + i_ * 128;                                            \
            int row = idx >> 5; int c4 = (idx & 31) * 4;                         \
            *(float4*)&rs[p][row * 132 + c4] =                                   \
                *(const float4*)&R[(size_t)(kd0 + (c) * 32 + row) * OO + o0 + c4];\
        }                                                                        \
    } while (0)

    LOAD_CHUNK(0, 0);
    __syncthreads();

    for (int c = 0; c < 32; c++) {
        const int cur = c & 1;
        if (c + 1 < 32) LOAD_CHUNK(c + 1, cur ^ 1);

#pragma unroll 8
        for (int kd = 0; kd < 32; kd++) {
            float4 vv  = *(float4*)&vs[cur][kd * 36 + bq * 4];
            float4 rv0 = *(float4*)&rs[cur][kd * 132 + oq * 8];
            float4 rv1 = *(float4*)&rs[cur][kd * 132 + oq * 8 + 4];
            acc[0][0] = fmaf(vv.x, rv0.x, acc[0][0]);
            acc[0][1] = fmaf(vv.x, rv0.y, acc[0][1]);
            acc[0][2] = fmaf(vv.x, rv0.z, acc[0][2]);
            acc[0][3] = fmaf(vv.x, rv0.w, acc[0][3]);
            acc[0][4] = fmaf(vv.x, rv1.x, acc[0][4]);
            acc[0][5] = fmaf(vv.x, rv1.y, acc[0][5]);
            acc[0][6] = fmaf(vv.x, rv1.z, acc[0][6]);
            acc[0][7] = fmaf(vv.x, rv1.w, acc[0][7]);
            acc[1][0] = fmaf(vv.y, rv0.x, acc[1][0]);
            acc[1][1] = fmaf(vv.y, rv0.y, acc[1][1]);
            acc[1][2] = fmaf(vv.y, rv0.z, acc[1][2]);
            acc[1][3] = fmaf(vv.y, rv0.w, acc[1][3]);
            acc[1][4] = fmaf(vv.y, rv1.x, acc[1][4]);
            acc[1][5] = fmaf(vv.y, rv1.y, acc[1][5]);
            acc[1][6] = fmaf(vv.y, rv1.z, acc[1][6]);
            acc[1][7] = fmaf(vv.y, rv1.w, acc[1][7]);
            acc[2][0] = fmaf(vv.z, rv0.x, acc[2][0]);
            acc[2][1] = fmaf(vv.z, rv0.y, acc[2][1]);
            acc[2][2] = fmaf(vv.z, rv0.z, acc[2][2]);
            acc[2][3] = fmaf(vv.z, rv0.w, acc[2][3]);
            acc[2][4] = fmaf(vv.z, rv1.x, acc[2][4]);
            acc[2][5] = fmaf(vv.z, rv1.y, acc[2][5]);
            acc[2][6] = fmaf(vv.z, rv1.z, acc[2][6]);
            acc[2][7] = fmaf(vv.z, rv1.w, acc[2][7]);
            acc[3][0] = fmaf(vv.w, rv0.x, acc[3][0]);
            acc[3][1] = fmaf(vv.w, rv0.y, acc[3][1]);
            acc[3][2] = fmaf(vv.w, rv0.z, acc[3][2]);
            acc[3][3] = fmaf(vv.w, rv0.w, acc[3][3]);
            acc[3][4] = fmaf(vv.w, rv1.x, acc[3][4]);
            acc[3][5] = fmaf(vv.w, rv1.y, acc[3][5]);
            acc[3][6] = fmaf(vv.w, rv1.z, acc[3][6]);
            acc[3][7] = fmaf(vv.w, rv1.w, acc[3][7]);
        }
        __syncthreads();
    }
#undef LOAD_CHUNK

#pragma unroll
    for (int i = 0; i < 4; i++)
#pragma unroll
        for (int j = 0; j < 8; j++)
            atomicAdd(&out[(size_t)(bq * 4 + i) * OO + o0 + oq * 8 + j], acc[i][j]);
}

// ---------------------------------------------------------------------------
// K5: apply second L2-normalize scale (linear, folded after GEMM)
// ---------------------------------------------------------------------------
__global__ __launch_bounds__(256) void k_finish(float* __restrict__ out) {
    int i = blockIdx.x * 256 + threadIdx.x;   // 32768 = B*O
    int b = i >> 10;
    out[i] *= rsqrtf(fmaxf(g_norm2[b], F_EPS));
}

extern "C" void kernel_launch(void* const* d_in, const int* in_sizes, int n_in,
                              void* d_out, int out_size) {
    const float* x       = (const float*)d_in[0];
    const float* w       = (const float*)d_in[1];
    const float* bias    = (const float*)d_in[2];
    const float* centers = (const float*)d_in[3];
    const float* R       = (const float*)d_in[4];
    float* out = (float*)d_out;

    void *p_agg, *p_sumw, *p_norm2;
    cudaGetSymbolAddress(&p_agg, g_agg);
    cudaGetSymbolAddress(&p_sumw, g_sumw);
    cudaGetSymbolAddress(&p_norm2, g_norm2);

    cudaMemsetAsync(p_agg, 0, sizeof(float) * BB * KK * DD);
    cudaMemsetAsync(p_sumw, 0, sizeof(float) * BB * KK);
    cudaMemsetAsync(p_norm2, 0, sizeof(float) * BB);
    cudaMemsetAsync(d_out, 0, sizeof(float) * BB * OO);

    k_assign<<<256, 256>>>(x, w, bias);
    k_agg<<<512, 128>>>(x);
    k_norm<<<2048, 128>>>(centers);
    k_out<<<256, 128>>>(R, out);
    k_finish<<<128, 256>>>(out);
}

// round 3
// speedup vs baseline: 1.0654x; 1.0654x over previous
#include <cuda_runtime.h>
#include <math.h>

#define BB 32
#define TT 1024
#define DD 512
#define KK 64
#define OO 1024
#define F_EPS 1e-12f

typedef unsigned long long ull;

// Packed f32x2 helpers (Blackwell 2x fp32 path; ptxas never auto-emits FFMA2)
__device__ __forceinline__ ull pack2(float v) {
    ull r;
    asm("mov.b64 %0, {%1, %1};" : "=l"(r) : "f"(v));
    return r;
}
__device__ __forceinline__ void ffma2(ull& d, ull a, ull b) {
    asm("fma.rn.f32x2 %0, %1, %2, %0;" : "+l"(d) : "l"(a), "l"(b));
}
__device__ __forceinline__ float2 unpack2(ull v) {
    float2 f;
    asm("mov.b64 {%0, %1}, %2;" : "=f"(f.x), "=f"(f.y) : "l"(v));
    return f;
}

// Scratch (device globals — no allocation allowed)
__device__ float g_a[BB * TT * KK];      // soft-assign [B,T,K]  (8 MB)
__device__ float g_agg[BB * KK * DD];    // x_agg [B,K,D] (4 MB)
__device__ float g_vt[KK * DD * BB];     // normalized v, TRANSPOSED [kd][b] (4 MB)
__device__ float g_sumw[BB * KK];        // per-(b,k) soft weight sums
__device__ float g_norm2[BB];            // per-b squared norm after intra-norm

// ---------------------------------------------------------------------------
// K1: logits = x @ W + bias, softmax over K, write a, accumulate sum_w.
// Block: 128 rows x 64 centers, 256 threads, thread tile 4 rows x 8 k (4 k-pairs).
// ---------------------------------------------------------------------------
__global__ __launch_bounds__(256) void k_assign(const float* __restrict__ x,
                                                const float* __restrict__ w,
                                                const float* __restrict__ bias) {
    __shared__ float xs[128 * 33];
    __shared__ __align__(16) float ws[32 * 64];
    __shared__ float bias_s[64];
    __shared__ float ssum[64];

    const int tid = threadIdx.x;
    const int r0 = blockIdx.x * 128;          // global row base (b*T + t)
    const int kg = tid & 7;                   // k-group (8 groups of 8 k)
    const int rg = tid >> 3;                  // row-group (32 groups of 4 rows)
    const int k8 = kg * 8;
    const int r4 = rg * 4;

    if (tid < 64) { ssum[tid] = 0.0f; bias_s[tid] = bias[tid]; }

    ull acc2[4][4];
#pragma unroll
    for (int i = 0; i < 4; i++)
#pragma unroll
        for (int j = 0; j < 4; j++) acc2[i][j] = 0ull;

    for (int d0 = 0; d0 < DD; d0 += 32) {
        // x tile [128 rows x 32 d] (padded stride 33)
#pragma unroll
        for (int i = 0; i < 4; i++) {
            int idx = tid + i * 256;          // float4 index 0..1023
            int row = idx >> 3;
            int dc  = (idx & 7) * 4;
            float4 v = *(const float4*)&x[(size_t)(r0 + row) * DD + d0 + dc];
            xs[row * 33 + dc + 0] = v.x;
            xs[row * 33 + dc + 1] = v.y;
            xs[row * 33 + dc + 2] = v.z;
            xs[row * 33 + dc + 3] = v.w;
        }
        // W tile: 2048 contiguous floats at w + d0*64
#pragma unroll
        for (int i = 0; i < 2; i++) {
            int idx = tid + i * 256;
            *(float4*)&ws[idx * 4] = *(const float4*)&w[(size_t)d0 * KK + idx * 4];
        }
        __syncthreads();

#pragma unroll 4
        for (int d = 0; d < 32; d++) {
            ulonglong2 w01 = *(const ulonglong2*)&ws[d * 64 + k8];
            ulonglong2 w23 = *(const ulonglong2*)&ws[d * 64 + k8 + 4];
#pragma unroll
            for (int i = 0; i < 4; i++) {
                ull xp = pack2(xs[(r4 + i) * 33 + d]);
                ffma2(acc2[i][0], xp, w01.x);
                ffma2(acc2[i][1], xp, w01.y);
                ffma2(acc2[i][2], xp, w23.x);
                ffma2(acc2[i][3], xp, w23.y);
            }
        }
        __syncthreads();
    }

    // softmax per row: 64 logits spread over 8 lanes (kg) x 8 regs
    float colsum[8];
#pragma unroll
    for (int j = 0; j < 8; j++) colsum[j] = 0.0f;
#pragma unroll
    for (int i = 0; i < 4; i++) {
        float v[8];
#pragma unroll
        for (int j = 0; j < 4; j++) {
            float2 p = unpack2(acc2[i][j]);
            v[j * 2 + 0] = p.x;
            v[j * 2 + 1] = p.y;
        }
        float m = -1e30f;
#pragma unroll
        for (int j = 0; j < 8; j++) {
            v[j] += bias_s[k8 + j];
            m = fmaxf(m, v[j]);
        }
#pragma unroll
        for (int off = 4; off > 0; off >>= 1)
            m = fmaxf(m, __shfl_xor_sync(0xffffffffu, m, off));
        float s = 0.0f;
#pragma unroll
        for (int j = 0; j < 8; j++) { v[j] = __expf(v[j] - m); s += v[j]; }
#pragma unroll
        for (int off = 4; off > 0; off >>= 1)
            s += __shfl_xor_sync(0xffffffffu, s, off);
        float inv = 1.0f / s;
        float4 a0, a1;
        a0.x = v[0] * inv; a0.y = v[1] * inv; a0.z = v[2] * inv; a0.w = v[3] * inv;
        a1.x = v[4] * inv; a1.y = v[5] * inv; a1.z = v[6] * inv; a1.w = v[7] * inv;
        colsum[0] += a0.x; colsum[1] += a0.y; colsum[2] += a0.z; colsum[3] += a0.w;
        colsum[4] += a1.x; colsum[5] += a1.y; colsum[6] += a1.z; colsum[7] += a1.w;
        *(float4*)&g_a[(size_t)(r0 + r4 + i) * KK + k8] = a0;
        *(float4*)&g_a[(size_t)(r0 + r4 + i) * KK + k8 + 4] = a1;
    }

    // reduce colsum over the 4 rg-groups in this warp, then smem atomics
#pragma unroll
    for (int j = 0; j < 8; j++) {
        colsum[j] += __shfl_xor_sync(0xffffffffu, colsum[j], 8);
        colsum[j] += __shfl_xor_sync(0xffffffffu, colsum[j], 16);
    }
    if ((tid & 31) < 8) {
#pragma unroll
        for (int j = 0; j < 8; j++) atomicAdd(&ssum[k8 + j], colsum[j]);
    }
    __syncthreads();
    if (tid < 64) atomicAdd(&g_sumw[(r0 >> 10) * KK + tid], ssum[tid]);
}

// ---------------------------------------------------------------------------
// K2: x_agg[b,k,d] = sum_t a[b,t,k] * x[b,t,d]
// grid: b(32) x dtile(4 of 128) x tseg(4 of 256) = 512 blocks, 128 threads.
// Each thread owns one d; 32 packed k-pair accumulators (f32x2).
// ---------------------------------------------------------------------------
__global__ __launch_bounds__(128) void k_agg(const float* __restrict__ x) {
    __shared__ __align__(16) float as[16 * 64];
    const int tid = threadIdx.x;
    const int bx = blockIdx.x;
    const int b   = bx >> 4;
    const int dt  = (bx >> 2) & 3;
    const int seg = bx & 3;
    const int d   = dt * 128 + tid;
    const int t0  = seg * 256;

    ull acc2[32];
#pragma unroll
    for (int k = 0; k < 32; k++) acc2[k] = 0ull;

    for (int tt0 = 0; tt0 < 256; tt0 += 16) {
#pragma unroll
        for (int i = 0; i < 2; i++) {
            int idx = tid + i * 128;
            *(float4*)&as[idx * 4] =
                *(const float4*)&g_a[(size_t)(b * TT + t0 + tt0) * KK + idx * 4];
        }
        __syncthreads();
#pragma unroll 2
        for (int tt = 0; tt < 16; tt++) {
            ull xp = pack2(x[(size_t)(b * TT + t0 + tt0 + tt) * DD + d]);
#pragma unroll
            for (int kk = 0; kk < 16; kk++) {
                ulonglong2 av = *(const ulonglong2*)&as[tt * 64 + kk * 4];
                ffma2(acc2[kk * 2 + 0], av.x, xp);
                ffma2(acc2[kk * 2 + 1], av.y, xp);
            }
        }
        __syncthreads();
    }
#pragma unroll
    for (int k = 0; k < 32; k++) {
        float2 p = unpack2(acc2[k]);
        atomicAdd(&g_agg[((size_t)b * KK + k * 2 + 0) * DD + d], p.x);
        atomicAdd(&g_agg[((size_t)b * KK + k * 2 + 1) * DD + d], p.y);
    }
}

// ---------------------------------------------------------------------------
// K3: residual + intra L2-normalize per (b,k); write v TRANSPOSED to g_vt[kd][b]
// ---------------------------------------------------------------------------
__global__ __launch_bounds__(128) void k_norm(const float* __restrict__ centers) {
    const int bx = blockIdx.x;                // 2048 = B*K
    const int b = bx >> 6;
    const int k = bx & 63;
    const int tid = threadIdx.x;

    const float sw = g_sumw[b * KK + k];
    const size_t base = ((size_t)b * KK + k) * DD;

    float4 xa = *(float4*)&g_agg[base + tid * 4];
    float4 c  = *(const float4*)&centers[(size_t)k * DD + tid * 4];
    float4 f;
    f.x = xa.x - sw * c.x;
    f.y = xa.y - sw * c.y;
    f.z = xa.z - sw * c.z;
    f.w = xa.w - sw * c.w;
    float ss = f.x * f.x + f.y * f.y + f.z * f.z + f.w * f.w;

#pragma unroll
    for (int off = 16; off > 0; off >>= 1)
        ss += __shfl_xor_sync(0xffffffffu, ss, off);

    __shared__ float wsum[4];
    __shared__ float scale_s;
    if ((tid & 31) == 0) wsum[tid >> 5] = ss;
    __syncthreads();
    if (tid == 0) {
        float tot = wsum[0] + wsum[1] + wsum[2] + wsum[3];
        float sc = rsqrtf(fmaxf(tot, F_EPS));
        scale_s = sc;
        atomicAdd(&g_norm2[b], tot * sc * sc);
    }
    __syncthreads();
    float sc = scale_s;
    const int d = tid * 4;
    const size_t vbase = ((size_t)k * DD + d) * BB + b;
    g_vt[vbase + 0 * BB] = f.x * sc;
    g_vt[vbase + 1 * BB] = f.y * sc;
    g_vt[vbase + 2 * BB] = f.z * sc;
    g_vt[vbase + 3 * BB] = f.w * sc;
}

// ---------------------------------------------------------------------------
// K4: out[b,o] += sum_kd v[b,kd] * R[kd,o]
// grid: 8 o-tiles(128) x 64 kd-chunks(512) = 512 blocks, 128 threads.
// Thread tile: 4 b x 8 o (4 o-pairs, f32x2). Double-buffered smem.
// ---------------------------------------------------------------------------
__global__ __launch_bounds__(128) void k_out(const float* __restrict__ R,
                                             float* __restrict__ out) {
    __shared__ __align__(16) float vs[2][32 * 36];   // [kd][b]
    __shared__ __align__(16) float rs[2][32 * 132];  // [kd][o]

    const int tid = threadIdx.x;
    const int bx = blockIdx.x;
    const int o0  = (bx & 7) * 128;
    const int kd0 = (bx >> 3) * 512;
    const int bq = tid & 7;        // b = bq*4 + i
    const int oq = tid >> 3;       // o = o0 + oq*8 + j

    ull acc2[4][4];
#pragma unroll
    for (int i = 0; i < 4; i++)
#pragma unroll
        for (int j = 0; j < 4; j++) acc2[i][j] = 0ull;

#define LOAD_CHUNK(c, p)                                                         \
    do {                                                                         \
        const float4* vsrc = (const float4*)&g_vt[(size_t)(kd0 + (c) * 32) * BB];\
        _Pragma("unroll")                                                        \
        for (int i_ = 0; i_ < 2; i_++) {                                         \
            int idx = tid + i_ * 128;                                            \
            int kd = idx >> 3; int bc = (idx & 7) * 4;                           \
            *(float4*)&vs[p][kd * 36 + bc] = vsrc[idx];                          \
        }                                                                        \
        _Pragma("unroll")                                                        \
        for (int i_ = 0; i_ < 8; i_++) {                                         \
            int idx = tid + i_ * 128;                                            \
            int row = idx >> 5; int c4 = (idx & 31) * 4;                         \
            *(float4*)&rs[p][row * 132 + c4] =                                   \
                *(const float4*)&R[(size_t)(kd0 + (c) * 32 + row) * OO + o0 + c4];\
        }                                                                        \
    } while (0)

    LOAD_CHUNK(0, 0);
    __syncthreads();

    for (int c = 0; c < 16; c++) {
        const int cur = c & 1;
        if (c + 1 < 16) LOAD_CHUNK(c + 1, cur ^ 1);

#pragma unroll 8
        for (int kd = 0; kd < 32; kd++) {
            float4 vv  = *(float4*)&vs[cur][kd * 36 + bq * 4];
            ulonglong2 r01 = *(const ulonglong2*)&rs[cur][kd * 132 + oq * 8];
            ulonglong2 r23 = *(const ulonglong2*)&rs[cur][kd * 132 + oq * 8 + 4];
            ull vp0 = pack2(vv.x);
            ull vp1 = pack2(vv.y);
            ull vp2 = pack2(vv.z);
            ull vp3 = pack2(vv.w);
            ffma2(acc2[0][0], vp0, r01.x);
            ffma2(acc2[0][1], vp0, r01.y);
            ffma2(acc2[0][2], vp0, r23.x);
            ffma2(acc2[0][3], vp0, r23.y);
            ffma2(acc2[1][0], vp1, r01.x);
            ffma2(acc2[1][1], vp1, r01.y);
            ffma2(acc2[1][2], vp1, r23.x);
            ffma2(acc2[1][3], vp1, r23.y);
            ffma2(acc2[2][0], vp2, r01.x);
            ffma2(acc2[2][1], vp2, r01.y);
            ffma2(acc2[2][2], vp2, r23.x);
            ffma2(acc2[2][3], vp2, r23.y);
            ffma2(acc2[3][0], vp3, r01.x);
            ffma2(acc2[3][1], vp3, r01.y);
            ffma2(acc2[3][2], vp3, r23.x);
            ffma2(acc2[3][3], vp3, r23.y);
        }
        __syncthreads();
    }
#undef LOAD_CHUNK

#pragma unroll
    for (int i = 0; i < 4; i++)
#pragma unroll
        for (int j = 0; j < 4; j++) {
            float2 p = unpack2(acc2[i][j]);
            atomicAdd(&out[(size_t)(bq * 4 + i) * OO + o0 + oq * 8 + j * 2 + 0], p.x);
            atomicAdd(&out[(size_t)(bq * 4 + i) * OO + o0 + oq * 8 + j * 2 + 1], p.y);
        }
}

// ---------------------------------------------------------------------------
// K5: apply second L2-normalize scale (linear, folded after GEMM)
// ---------------------------------------------------------------------------
__global__ __launch_bounds__(256) void k_finish(float* __restrict__ out) {
    int i = blockIdx.x * 256 + threadIdx.x;   // 32768 = B*O
    int b = i >> 10;
    out[i] *= rsqrtf(fmaxf(g_norm2[b], F_EPS));
}

extern "C" void kernel_launch(void* const* d_in, const int* in_sizes, int n_in,
                              void* d_out, int out_size) {
    const float* x       = (const float*)d_in[0];
    const float* w       = (const float*)d_in[1];
    const float* bias    = (const float*)d_in[2];
    const float* centers = (const float*)d_in[3];
    const float* R       = (const float*)d_in[4];
    float* out = (float*)d_out;

    void *p_agg, *p_sumw, *p_norm2;
    cudaGetSymbolAddress(&p_agg, g_agg);
    cudaGetSymbolAddress(&p_sumw, g_sumw);
    cudaGetSymbolAddress(&p_norm2, g_norm2);

    cudaMemsetAsync(p_agg, 0, sizeof(float) * BB * KK * DD);
    cudaMemsetAsync(p_sumw, 0, sizeof(float) * BB * KK);
    cudaMemsetAsync(p_norm2, 0, sizeof(float) * BB);
    cudaMemsetAsync(d_out, 0, sizeof(float) * BB * OO);

    k_assign<<<256, 256>>>(x, w, bias);
    k_agg<<<512, 128>>>(x);
    k_norm<<<2048, 128>>>(centers);
    k_out<<<512, 128>>>(R, out);
    k_finish<<<128, 256>>>(out);
}

// round 5
// speedup vs baseline: 1.3788x; 1.2942x over previous
#include <cuda_runtime.h>
#include <math.h>

#define BB 32
#define TT 1024
#define DD 512
#define KK 64
#define OO 1024
#define F_EPS 1e-12f

typedef unsigned long long ull;

__device__ __forceinline__ ull pack2(float v) {
    ull r;
    asm("mov.b64 %0, {%1, %1};" : "=l"(r) : "f"(v));
    return r;
}
__device__ __forceinline__ void ffma2(ull& d, ull a, ull b) {
    asm("fma.rn.f32x2 %0, %1, %2, %0;" : "+l"(d) : "l"(a), "l"(b));
}
__device__ __forceinline__ float2 unpack2(ull v) {
    float2 f;
    asm("mov.b64 {%0, %1}, %2;" : "=f"(f.x), "=f"(f.y) : "l"(v));
    return f;
}

// Scratch
__device__ float g_a[BB * TT * KK];      // soft-assign [B,T,K]
__device__ float g_agg[BB * KK * DD];    // x_agg [B,K,D]
__device__ float g_vt[KK * DD * BB];     // normalized v, transposed [kd][b]
__device__ float g_sumw[BB * KK];
__device__ float g_norm2[BB];

// ---------------------------------------------------------------------------
// K1: logits = x@W + bias -> softmax -> a, sum_w.
// Block: 128 rows x 64 k, 128 threads, thread tile 8r x 8k, d-chunk 16, dbuf.
// ---------------------------------------------------------------------------
__global__ __launch_bounds__(128) void k_assign(const float* __restrict__ x,
                                                const float* __restrict__ w,
                                                const float* __restrict__ bias) {
    __shared__ __align__(16) float xs_t[2][16 * 132];  // [d][r], pad 132
    __shared__ __align__(16) float ws[2][16 * 68];     // [d][k], pad 68
    __shared__ float bias_s[64];
    __shared__ float ssum[64];

    const int tid = threadIdx.x;
    const int r0 = blockIdx.x * 128;
    const int kq = tid & 7;       // k-group: k = kq*8 + j
    const int rq = tid >> 3;      // r-group: r = r0 + rq*8 + i
    const int b  = r0 >> 10;

    if (tid < 64) { ssum[tid] = 0.0f; bias_s[tid] = bias[tid]; }

    ull acc2[8][4];
#pragma unroll
    for (int i = 0; i < 8; i++)
#pragma unroll
        for (int j = 0; j < 4; j++) acc2[i][j] = 0ull;

    float4 px[4], pw[2];

#define K1_LDG(d0)                                                              \
    do {                                                                        \
        _Pragma("unroll")                                                       \
        for (int i_ = 0; i_ < 4; i_++) {                                        \
            int idx = tid + i_ * 128;                                           \
            int row = idx >> 2, dc = (idx & 3) * 4;                             \
            px[i_] = *(const float4*)&x[(size_t)(r0 + row) * DD + (d0) + dc];   \
        }                                                                       \
        _Pragma("unroll")                                                       \
        for (int i_ = 0; i_ < 2; i_++) {                                        \
            int idx = tid + i_ * 128;                                           \
            int dl = idx >> 4, kc = (idx & 15) * 4;                             \
            pw[i_] = *(const float4*)&w[(size_t)((d0) + dl) * KK + kc];         \
        }                                                                       \
    } while (0)

#define K1_STS(p)                                                               \
    do {                                                                        \
        _Pragma("unroll")                                                       \
        for (int i_ = 0; i_ < 4; i_++) {                                        \
            int idx = tid + i_ * 128;                                           \
            int row = idx >> 2, dc = (idx & 3) * 4;                             \
            xs_t[p][(dc + 0) * 132 + row] = px[i_].x;                           \
            xs_t[p][(dc + 1) * 132 + row] = px[i_].y;                           \
            xs_t[p][(dc + 2) * 132 + row] = px[i_].z;                           \
            xs_t[p][(dc + 3) * 132 + row] = px[i_].w;                           \
        }                                                                       \
        _Pragma("unroll")                                                       \
        for (int i_ = 0; i_ < 2; i_++) {                                        \
            int idx = tid + i_ * 128;                                           \
            int dl = idx >> 4, kc = (idx & 15) * 4;                             \
            *(float4*)&ws[p][dl * 68 + kc] = pw[i_];                            \
        }                                                                       \
    } while (0)

    K1_LDG(0);
    K1_STS(0);
    __syncthreads();

    const int NC = DD / 16;   // 32 chunks
    for (int c = 0; c < NC; c++) {
        const int cur = c & 1;
        if (c + 1 < NC) K1_LDG((c + 1) * 16);

#pragma unroll
        for (int d = 0; d < 16; d++) {
            ulonglong2 w01 = *(const ulonglong2*)&ws[cur][d * 68 + kq * 8];
            ulonglong2 w23 = *(const ulonglong2*)&ws[cur][d * 68 + kq * 8 + 4];
            float4 x0 = *(const float4*)&xs_t[cur][d * 132 + rq * 8];
            float4 x1 = *(const float4*)&xs_t[cur][d * 132 + rq * 8 + 4];
            ull xp[8];
            xp[0] = pack2(x0.x); xp[1] = pack2(x0.y);
            xp[2] = pack2(x0.z); xp[3] = pack2(x0.w);
            xp[4] = pack2(x1.x); xp[5] = pack2(x1.y);
            xp[6] = pack2(x1.z); xp[7] = pack2(x1.w);
#pragma unroll
            for (int i = 0; i < 8; i++) {
                ffma2(acc2[i][0], xp[i], w01.x);
                ffma2(acc2[i][1], xp[i], w01.y);
                ffma2(acc2[i][2], xp[i], w23.x);
                ffma2(acc2[i][3], xp[i], w23.y);
            }
        }
        if (c + 1 < NC) K1_STS(cur ^ 1);
        __syncthreads();
    }
#undef K1_LDG
#undef K1_STS

    // softmax per row: 64 logits over 8 lanes (kq) x 8 regs
    float colsum[8];
#pragma unroll
    for (int j = 0; j < 8; j++) colsum[j] = 0.0f;
#pragma unroll
    for (int i = 0; i < 8; i++) {
        float v[8];
#pragma unroll
        for (int j = 0; j < 4; j++) {
            float2 p = unpack2(acc2[i][j]);
            v[j * 2 + 0] = p.x;
            v[j * 2 + 1] = p.y;
        }
        float m = -1e30f;
#pragma unroll
        for (int j = 0; j < 8; j++) {
            v[j] += bias_s[kq * 8 + j];
            m = fmaxf(m, v[j]);
        }
#pragma unroll
        for (int off = 4; off > 0; off >>= 1)
            m = fmaxf(m, __shfl_xor_sync(0xffffffffu, m, off));
        float s = 0.0f;
#pragma unroll
        for (int j = 0; j < 8; j++) { v[j] = __expf(v[j] - m); s += v[j]; }
#pragma unroll
        for (int off = 4; off > 0; off >>= 1)
            s += __shfl_xor_sync(0xffffffffu, s, off);
        float inv = 1.0f / s;
        float4 a0, a1;
        a0.x = v[0] * inv; a0.y = v[1] * inv; a0.z = v[2] * inv; a0.w = v[3] * inv;
        a1.x = v[4] * inv; a1.y = v[5] * inv; a1.z = v[6] * inv; a1.w = v[7] * inv;
        colsum[0] += a0.x; colsum[1] += a0.y; colsum[2] += a0.z; colsum[3] += a0.w;
        colsum[4] += a1.x; colsum[5] += a1.y; colsum[6] += a1.z; colsum[7] += a1.w;
        size_t row = (size_t)(r0 + rq * 8 + i);
        *(float4*)&g_a[row * KK + kq * 8] = a0;
        *(float4*)&g_a[row * KK + kq * 8 + 4] = a1;
    }

#pragma unroll
    for (int j = 0; j < 8; j++) {
        colsum[j] += __shfl_xor_sync(0xffffffffu, colsum[j], 8);
        colsum[j] += __shfl_xor_sync(0xffffffffu, colsum[j], 16);
    }
    if ((tid & 31) < 8) {
#pragma unroll
        for (int j = 0; j < 8; j++) atomicAdd(&ssum[kq * 8 + j], colsum[j]);
    }
    __syncthreads();
    if (tid < 64) atomicAdd(&g_sumw[b * KK + tid], ssum[tid]);
}

// ---------------------------------------------------------------------------
// K2: x_agg[b,k,d] = sum_t a[b,t,k] x[b,t,d]
// Block: 64k x 128d, 128 threads, thread tile 8k x 8d, t-chunk 16, dbuf.
// grid: b(32) x dtile(4) x tseg(2) = 256 blocks.
// ---------------------------------------------------------------------------
__global__ __launch_bounds__(128) void k_agg(const float* __restrict__ x) {
    __shared__ __align__(16) float as[2][16 * 68];    // [t][k]
    __shared__ __align__(16) float xs[2][16 * 132];   // [t][d]

    const int tid = threadIdx.x;
    const int bx = blockIdx.x;
    const int b   = bx >> 3;
    const int dt  = (bx >> 1) & 3;
    const int seg = bx & 1;
    const int t0  = seg * 512;
    const int kq2 = tid >> 4;     // k = kq2*8 + i
    const int dq  = tid & 15;     // d = dt*128 + dq*8 + j

    ull acc2[8][4];
#pragma unroll
    for (int i = 0; i < 8; i++)
#pragma unroll
        for (int j = 0; j < 4; j++) acc2[i][j] = 0ull;

    float4 pa[2], px[4];

#define K2_LDG(tb)                                                              \
    do {                                                                        \
        _Pragma("unroll")                                                       \
        for (int i_ = 0; i_ < 2; i_++) {                                        \
            int idx = tid + i_ * 128;                                           \
            int row = idx >> 4, col = (idx & 15) * 4;                           \
            pa[i_] = *(const float4*)&g_a[(size_t)(b * TT + (tb) + row) * KK + col]; \
        }                                                                       \
        _Pragma("unroll")                                                       \
        for (int i_ = 0; i_ < 4; i_++) {                                        \
            int idx = tid + i_ * 128;                                           \
            int row = idx >> 5, col = (idx & 31) * 4;                           \
            px[i_] = *(const float4*)&x[(size_t)(b * TT + (tb) + row) * DD + dt * 128 + col]; \
        }                                                                       \
    } while (0)

#define K2_STS(p)                                                               \
    do {                                                                        \
        _Pragma("unroll")                                                       \
        for (int i_ = 0; i_ < 2; i_++) {                                        \
            int idx = tid + i_ * 128;                                           \
            int row = idx >> 4, col = (idx & 15) * 4;                           \
            *(float4*)&as[p][row * 68 + col] = pa[i_];                          \
        }                                                                       \
        _Pragma("unroll")                                                       \
        for (int i_ = 0; i_ < 4; i_++) {                                        \
            int idx = tid + i_ * 128;                                           \
            int row = idx >> 5, col = (idx & 31) * 4;                           \
            *(float4*)&xs[p][row * 132 + col] = px[i_];                         \
        }                                                                       \
    } while (0)

    K2_LDG(t0);
    K2_STS(0);
    __syncthreads();

    const int NC = 512 / 16;   // 32 chunks
    for (int c = 0; c < NC; c++) {
        const int cur = c & 1;
        if (c + 1 < NC) K2_LDG(t0 + (c + 1) * 16);

#pragma unroll
        for (int t = 0; t < 16; t++) {
            float4 a0 = *(const float4*)&as[cur][t * 68 + kq2 * 8];
            float4 a1 = *(const float4*)&as[cur][t * 68 + kq2 * 8 + 4];
            ulonglong2 x01 = *(const ulonglong2*)&xs[cur][t * 132 + dq * 8];
            ulonglong2 x23 = *(const ulonglong2*)&xs[cur][t * 132 + dq * 8 + 4];
            ull ap[8];
            ap[0] = pack2(a0.x); ap[1] = pack2(a0.y);
            ap[2] = pack2(a0.z); ap[3] = pack2(a0.w);
            ap[4] = pack2(a1.x); ap[5] = pack2(a1.y);
            ap[6] = pack2(a1.z); ap[7] = pack2(a1.w);
#pragma unroll
            for (int i = 0; i < 8; i++) {
                ffma2(acc2[i][0], ap[i], x01.x);
                ffma2(acc2[i][1], ap[i], x01.y);
                ffma2(acc2[i][2], ap[i], x23.x);
                ffma2(acc2[i][3], ap[i], x23.y);
            }
        }
        if (c + 1 < NC) K2_STS(cur ^ 1);
        __syncthreads();
    }
#undef K2_LDG
#undef K2_STS

#pragma unroll
    for (int i = 0; i < 8; i++)
#pragma unroll
        for (int j = 0; j < 4; j++) {
            float2 p = unpack2(acc2[i][j]);
            size_t base = ((size_t)b * KK + kq2 * 8 + i) * DD + dt * 128 + dq * 8 + j * 2;
            atomicAdd(&g_agg[base + 0], p.x);
            atomicAdd(&g_agg[base + 1], p.y);
        }
}

// ---------------------------------------------------------------------------
// K3: residual + intra L2-normalize; write v transposed to g_vt[kd][b]
// ---------------------------------------------------------------------------
__global__ __launch_bounds__(128) void k_norm(const float* __restrict__ centers) {
    const int bx = blockIdx.x;                // 2048 = B*K
    const int b = bx >> 6;
    const int k = bx & 63;
    const int tid = threadIdx.x;

    const float sw = g_sumw[b * KK + k];
    const size_t base = ((size_t)b * KK + k) * DD;

    float4 xa = *(float4*)&g_agg[base + tid * 4];
    float4 c  = *(const float4*)&centers[(size_t)k * DD + tid * 4];
    float4 f;
    f.x = xa.x - sw * c.x;
    f.y = xa.y - sw * c.y;
    f.z = xa.z - sw * c.z;
    f.w = xa.w - sw * c.w;
    float ss = f.x * f.x + f.y * f.y + f.z * f.z + f.w * f.w;

#pragma unroll
    for (int off = 16; off > 0; off >>= 1)
        ss += __shfl_xor_sync(0xffffffffu, ss, off);

    __shared__ float wsum[4];
    __shared__ float scale_s;
    if ((tid & 31) == 0) wsum[tid >> 5] = ss;
    __syncthreads();
    if (tid == 0) {
        float tot = wsum[0] + wsum[1] + wsum[2] + wsum[3];
        float sc = rsqrtf(fmaxf(tot, F_EPS));
        scale_s = sc;
        atomicAdd(&g_norm2[b], tot * sc * sc);
    }
    __syncthreads();
    float sc = scale_s;
    const int d = tid * 4;
    const size_t vbase = ((size_t)k * DD + d) * BB + b;
    g_vt[vbase + 0 * BB] = f.x * sc;
    g_vt[vbase + 1 * BB] = f.y * sc;
    g_vt[vbase + 2 * BB] = f.z * sc;
    g_vt[vbase + 3 * BB] = f.w * sc;
}

// ---------------------------------------------------------------------------
// K4: out[b,o] += sum_kd v[b,kd] R[kd,o]     (kd total = KK*DD = 32768)
// Block: 32b x 256o, 128 threads, thread tile 8b x 8o, kd-chunk 16, dbuf.
// grid: o-tiles(4) x kd-split(64 of 512) = 256 blocks; 32 chunks each.
// ---------------------------------------------------------------------------
__global__ __launch_bounds__(128) void k_out(const float* __restrict__ R,
                                             float* __restrict__ out) {
    __shared__ __align__(16) float vs[2][16 * 36];    // [kd][b]
    __shared__ __align__(16) float rs[2][16 * 260];   // [kd][o]

    const int tid = threadIdx.x;
    const int bx = blockIdx.x;
    const int o0  = (bx & 3) * 256;
    const int kd0 = (bx >> 2) * 512;
    const int bq = tid >> 5;       // b = bq*8 + i
    const int oq = tid & 31;       // o = o0 + oq*8 + j

    ull acc2[8][4];
#pragma unroll
    for (int i = 0; i < 8; i++)
#pragma unroll
        for (int j = 0; j < 4; j++) acc2[i][j] = 0ull;

    float4 pv, pr[8];

#define K4_LDG(c_)                                                              \
    do {                                                                        \
        {                                                                       \
            int row = tid >> 3, col = (tid & 7) * 4;                            \
            pv = *(const float4*)&g_vt[(size_t)(kd0 + (c_) * 16 + row) * BB + col]; \
        }                                                                       \
        _Pragma("unroll")                                                       \
        for (int i_ = 0; i_ < 8; i_++) {                                        \
            int idx = tid + i_ * 128;                                           \
            int row = idx >> 6, col = (idx & 63) * 4;                           \
            pr[i_] = *(const float4*)&R[(size_t)(kd0 + (c_) * 16 + row) * OO + o0 + col]; \
        }                                                                       \
    } while (0)

#define K4_STS(p)                                                               \
    do {                                                                        \
        {                                                                       \
            int row = tid >> 3, col = (tid & 7) * 4;                            \
            *(float4*)&vs[p][row * 36 + col] = pv;                              \
        }                                                                       \
        _Pragma("unroll")                                                       \
        for (int i_ = 0; i_ < 8; i_++) {                                        \
            int idx = tid + i_ * 128;                                           \
            int row = idx >> 6, col = (idx & 63) * 4;                           \
            *(float4*)&rs[p][row * 260 + col] = pr[i_];                         \
        }                                                                       \
    } while (0)

    K4_LDG(0);
    K4_STS(0);
    __syncthreads();

    const int NC = 32;   // 32 chunks x 16 kd = 512 kd per block
    for (int c = 0; c < NC; c++) {
        const int cur = c & 1;
        if (c + 1 < NC) K4_LDG(c + 1);

#pragma unroll
        for (int kd = 0; kd < 16; kd++) {
            float4 v0 = *(const float4*)&vs[cur][kd * 36 + bq * 8];
            float4 v1 = *(const float4*)&vs[cur][kd * 36 + bq * 8 + 4];
            ulonglong2 r01 = *(const ulonglong2*)&rs[cur][kd * 260 + oq * 8];
            ulonglong2 r23 = *(const ulonglong2*)&rs[cur][kd * 260 + oq * 8 + 4];
            ull vp[8];
            vp[0] = pack2(v0.x); vp[1] = pack2(v0.y);
            vp[2] = pack2(v0.z); vp[3] = pack2(v0.w);
            vp[4] = pack2(v1.x); vp[5] = pack2(v1.y);
            vp[6] = pack2(v1.z); vp[7] = pack2(v1.w);
#pragma unroll
            for (int i = 0; i < 8; i++) {
                ffma2(acc2[i][0], vp[i], r01.x);
                ffma2(acc2[i][1], vp[i], r01.y);
                ffma2(acc2[i][2], vp[i], r23.x);
                ffma2(acc2[i][3], vp[i], r23.y);
            }
        }
        if (c + 1 < NC) K4_STS(cur ^ 1);
        __syncthreads();
    }
#undef K4_LDG
#undef K4_STS

#pragma unroll
    for (int i = 0; i < 8; i++)
#pragma unroll
        for (int j = 0; j < 4; j++) {
            float2 p = unpack2(acc2[i][j]);
            size_t base = (size_t)(bq * 8 + i) * OO + o0 + oq * 8 + j * 2;
            atomicAdd(&out[base + 0], p.x);
            atomicAdd(&out[base + 1], p.y);
        }
}

// ---------------------------------------------------------------------------
// K5: apply second L2-normalize scale
// ---------------------------------------------------------------------------
__global__ __launch_bounds__(256) void k_finish(float* __restrict__ out) {
    int i = blockIdx.x * 256 + threadIdx.x;   // 32768 = B*O
    int b = i >> 10;
    out[i] *= rsqrtf(fmaxf(g_norm2[b], F_EPS));
}

extern "C" void kernel_launch(void* const* d_in, const int* in_sizes, int n_in,
                              void* d_out, int out_size) {
    const float* x       = (const float*)d_in[0];
    const float* w       = (const float*)d_in[1];
    const float* bias    = (const float*)d_in[2];
    const float* centers = (const float*)d_in[3];
    const float* R       = (const float*)d_in[4];
    float* out = (float*)d_out;

    void *p_agg, *p_sumw, *p_norm2;
    cudaGetSymbolAddress(&p_agg, g_agg);
    cudaGetSymbolAddress(&p_sumw, g_sumw);
    cudaGetSymbolAddress(&p_norm2, g_norm2);

    cudaMemsetAsync(p_agg, 0, sizeof(float) * BB * KK * DD);
    cudaMemsetAsync(p_sumw, 0, sizeof(float) * BB * KK);
    cudaMemsetAsync(p_norm2, 0, sizeof(float) * BB);
    cudaMemsetAsync(d_out, 0, sizeof(float) * BB * OO);

    k_assign<<<256, 128>>>(x, w, bias);
    k_agg<<<256, 128>>>(x);
    k_norm<<<2048, 128>>>(centers);
    k_out<<<256, 128>>>(R, out);
    k_finish<<<128, 256>>>(out);
}